// round 3
// baseline (speedup 1.0000x reference)
#include <cuda_runtime.h>
#include <cstdint>
#include <math.h>

#define NTOK 8192
#define DIM  1024
#define HID  256
#define HIDC 128
#define POOL 16384
#define TOPK 1024

// ---------------- scratch (device globals: no allocations allowed) ----------
__device__ float g_hs[NTOK * HID];                 // 8 MB
__device__ float g_hc[NTOK * HIDC];                // 4 MB
__device__ float g_scores[(size_t)NTOK * POOL];    // 512 MB
__device__ int   g_budget[NTOK];

// packed fp32x2 FMA (sm_100+): two independent rn-rounded fp32 FMAs per issue.
__device__ __forceinline__ float2 ffma2(float2 a, float2 b, float2 c) {
    unsigned long long A = *(unsigned long long*)&a;
    unsigned long long B = *(unsigned long long*)&b;
    unsigned long long C = *(unsigned long long*)&c;
    unsigned long long D;
    asm("fma.rn.f32x2 %0, %1, %2, %3;" : "=l"(D) : "l"(A), "l"(B), "l"(C));
    return *(float2*)&D;
}

// ---------------- fp32x2 tiled GEMM: C = (relu?)(A[MxK] @ B[KxN] + bias[N]) --
// BM=128, BN=128, BK=16, 256 threads, 8x8 outputs/thread.
// A tile stored DUPLICATED in smem: As[k][2m]=As[k][2m+1]=A[m][k], so the
// broadcast operand of fma.f32x2 loads directly as a pair (no MOV duplication).
// Each output element is ONE fp32 FMA chain in increasing k-order (bitwise-
// identical to scalar sequential accumulation -> matches reference/cublas).
template<bool RELU>
__global__ void __launch_bounds__(256, 2)
sgemm2_bias(const float* __restrict__ A, const float* __restrict__ B,
            const float* __restrict__ bias, float* __restrict__ C,
            int M, int N, int K)
{
    __shared__ float As[2][16][256];   // duplicated pairs: 32 KB
    __shared__ float Bs[2][16][128];   // 16 KB

    const int tid = threadIdx.x;
    const int bm  = blockIdx.y * 128;
    const int bn  = blockIdx.x * 128;
    const int tx  = tid & 15;
    const int ty  = tid >> 4;

    float2 acc[8][4];
#pragma unroll
    for (int i = 0; i < 8; i++)
#pragma unroll
        for (int q = 0; q < 4; q++) acc[i][q] = make_float2(0.f, 0.f);

    // staging coordinates
    const int ar = tid >> 1;            // A row within tile (0..127)
    const int ac = (tid & 1) * 8;       // A k-col group (0 or 8)
    const int br = tid >> 4;            // B k-row (0..15)
    const int bc = (tid & 15) * 8;      // B col group (0..120)
    const float* Aptr = A + (size_t)(bm + ar) * K + ac;
    const float* Bptr = B + (size_t)br * N + bn + bc;

    const int NT = K >> 4;

    // prologue: load tile 0
    float4 av0 = *(const float4*)(Aptr);
    float4 av1 = *(const float4*)(Aptr + 4);
    float4 bv0 = *(const float4*)(Bptr);
    float4 bv1 = *(const float4*)(Bptr + 4);
    {
        float a8[8] = {av0.x, av0.y, av0.z, av0.w, av1.x, av1.y, av1.z, av1.w};
#pragma unroll
        for (int i = 0; i < 8; i++)
            *(float2*)&As[0][ac + i][2 * ar] = make_float2(a8[i], a8[i]);
        *(float4*)&Bs[0][br][bc]     = bv0;
        *(float4*)&Bs[0][br][bc + 4] = bv1;
    }
    __syncthreads();

    for (int t = 0; t < NT; t++) {
        const int buf = t & 1;
        const bool more = (t + 1) < NT;
        if (more) {
            const float* Ap = Aptr + (t + 1) * 16;
            const float* Bp = Bptr + (size_t)(t + 1) * 16 * N;
            av0 = *(const float4*)(Ap);
            av1 = *(const float4*)(Ap + 4);
            bv0 = *(const float4*)(Bp);
            bv1 = *(const float4*)(Bp + 4);
        }

#pragma unroll
        for (int k = 0; k < 16; k++) {
            // duplicated A pairs: 16 consecutive floats = rows ty*8..ty*8+7
            float4 q0 = *(const float4*)&As[buf][k][ty * 16 + 0];
            float4 q1 = *(const float4*)&As[buf][k][ty * 16 + 4];
            float4 q2 = *(const float4*)&As[buf][k][ty * 16 + 8];
            float4 q3 = *(const float4*)&As[buf][k][ty * 16 + 12];
            float4 b0 = *(const float4*)&Bs[buf][k][tx * 4];
            float4 b1 = *(const float4*)&Bs[buf][k][tx * 4 + 64];
            float2 ad[8];
            ad[0] = make_float2(q0.x, q0.y); ad[1] = make_float2(q0.z, q0.w);
            ad[2] = make_float2(q1.x, q1.y); ad[3] = make_float2(q1.z, q1.w);
            ad[4] = make_float2(q2.x, q2.y); ad[5] = make_float2(q2.z, q2.w);
            ad[6] = make_float2(q3.x, q3.y); ad[7] = make_float2(q3.z, q3.w);
            float2 bp[4];
            bp[0] = make_float2(b0.x, b0.y); bp[1] = make_float2(b0.z, b0.w);
            bp[2] = make_float2(b1.x, b1.y); bp[3] = make_float2(b1.z, b1.w);
#pragma unroll
            for (int i = 0; i < 8; i++)
#pragma unroll
                for (int q = 0; q < 4; q++)
                    acc[i][q] = ffma2(ad[i], bp[q], acc[i][q]);
        }

        if (more) {
            const int nb = buf ^ 1;
            float a8[8] = {av0.x, av0.y, av0.z, av0.w, av1.x, av1.y, av1.z, av1.w};
#pragma unroll
            for (int i = 0; i < 8; i++)
                *(float2*)&As[nb][ac + i][2 * ar] = make_float2(a8[i], a8[i]);
            *(float4*)&Bs[nb][br][bc]     = bv0;
            *(float4*)&Bs[nb][br][bc + 4] = bv1;
        }
        __syncthreads();
    }

    // epilogue: bias (+relu), float4 stores
#pragma unroll
    for (int i = 0; i < 8; i++) {
        const int row = bm + ty * 8 + i;
#pragma unroll
        for (int g = 0; g < 2; g++) {
            const int col = bn + tx * 4 + g * 64;
            float4 v;
            v.x = acc[i][g * 2 + 0].x + bias[col + 0];
            v.y = acc[i][g * 2 + 0].y + bias[col + 1];
            v.z = acc[i][g * 2 + 1].x + bias[col + 2];
            v.w = acc[i][g * 2 + 1].y + bias[col + 3];
            if (RELU) {
                v.x = fmaxf(v.x, 0.f); v.y = fmaxf(v.y, 0.f);
                v.z = fmaxf(v.z, 0.f); v.w = fmaxf(v.w, 0.f);
            }
            *(float4*)(C + (size_t)row * N + col) = v;
        }
    }
}

// ---------------- complexity -> sigmoid -> budget ---------------------------
__global__ void complexity_kernel(const float* __restrict__ hc,
                                  const float* __restrict__ w2c,
                                  const float* __restrict__ b2c,
                                  float* __restrict__ out_c,
                                  int* __restrict__ budget)
{
    int warp = (blockIdx.x * blockDim.x + threadIdx.x) >> 5;
    int lane = threadIdx.x & 31;
    if (warp >= NTOK) return;
    const float* h = hc + (size_t)warp * HIDC;
    float s = 0.f;
#pragma unroll
    for (int i = lane; i < HIDC; i += 32) s += h[i] * w2c[i];
#pragma unroll
    for (int o = 16; o; o >>= 1) s += __shfl_xor_sync(0xFFFFFFFFu, s, o);
    if (lane == 0) {
        float z = s + b2c[0];
        float c = 1.f / (1.f + expf(-z));
        out_c[warp] = c;
        float raw = 100.f + 924.f * (c * c);
        raw = fminf(fmaxf(raw, 100.f), 1024.f);
        budget[warp] = (int)rintf(raw);
    }
}

// ---------------- per-token top-1024 (sorted) + softmax + mask --------------
__device__ __forceinline__ uint32_t f2mk(float f) {
    uint32_t u = __float_as_uint(f);
    return (u & 0x80000000u) ? ~u : (u | 0x80000000u);
}
__device__ __forceinline__ float mk2f(uint32_t mk) {
    uint32_t u = (mk & 0x80000000u) ? (mk ^ 0x80000000u) : ~mk;
    return __uint_as_float(u);
}

__global__ void __launch_bounds__(512)
topk_kernel(const float* __restrict__ scores, const int* __restrict__ budget,
            float* __restrict__ out_idx, float* __restrict__ out_w,
            float* __restrict__ out_m)
{
    __shared__ uint32_t hist[4096];
    __shared__ unsigned long long pairs[2048];
    __shared__ uint32_t chunksum[256];
    __shared__ uint32_t s_bstar, s_cnt;
    __shared__ float    s_red[512];

    const int t   = blockIdx.x;
    const int tid = threadIdx.x;
    const float* row = scores + (size_t)t * POOL;
    const float4* row4 = (const float4*)row;

    for (int i = tid; i < 4096; i += 512) hist[i] = 0;
    __syncthreads();

    // pass 1: 12-bit monotonic-key histogram (float4 loads)
#pragma unroll
    for (int s = 0; s < 8; s++) {
        float4 v = row4[tid + s * 512];
        atomicAdd(&hist[f2mk(v.x) >> 20], 1u);
        atomicAdd(&hist[f2mk(v.y) >> 20], 1u);
        atomicAdd(&hist[f2mk(v.z) >> 20], 1u);
        atomicAdd(&hist[f2mk(v.w) >> 20], 1u);
    }
    __syncthreads();

    if (tid < 256) {
        uint32_t cs = 0;
#pragma unroll
        for (int b = tid * 16; b < tid * 16 + 16; b++) cs += hist[b];
        chunksum[tid] = cs;
    }
    __syncthreads();

    if (tid == 0) {
        uint32_t acc = 0;
        int chunk = 255;
        for (; chunk > 0; chunk--) {
            if (acc + chunksum[chunk] >= TOPK) break;
            acc += chunksum[chunk];
        }
        int b = chunk * 16 + 15;
        for (; b > chunk * 16; b--) {
            if (acc + hist[b] >= TOPK) break;
            acc += hist[b];
        }
        s_bstar = (uint32_t)b;
        s_cnt   = 0;
    }
    __syncthreads();
    const uint32_t bstar = s_bstar;

    // pass 2: compact survivors; packed key: desc value, asc index
#pragma unroll
    for (int s = 0; s < 8; s++) {
        int i4 = tid + s * 512;
        float4 v = row4[i4];
        float vals[4] = {v.x, v.y, v.z, v.w};
#pragma unroll
        for (int e = 0; e < 4; e++) {
            uint32_t mk = f2mk(vals[e]);
            if ((mk >> 20) >= bstar) {
                uint32_t pos = atomicAdd(&s_cnt, 1u);
                if (pos < 2048) {
                    uint32_t idx = (uint32_t)(i4 * 4 + e);
                    pairs[pos] = ((unsigned long long)mk << 32) |
                                 (unsigned long long)(0xFFFFFFFFu - idx);
                }
            }
        }
    }
    __syncthreads();
    uint32_t cnt = s_cnt > 2048 ? 2048u : s_cnt;
    for (int i = tid; i < 2048; i += 512)
        if ((uint32_t)i >= cnt) pairs[i] = 0ull;
    __syncthreads();

    // bitonic sort 2048 u64, descending
    for (int k = 2; k <= 2048; k <<= 1) {
        for (int j = k >> 1; j > 0; j >>= 1) {
            for (int i = tid; i < 2048; i += 512) {
                int ixj = i ^ j;
                if (ixj > i) {
                    unsigned long long a = pairs[i], b = pairs[ixj];
                    bool desc = ((i & k) == 0);
                    if (desc ? (a < b) : (a > b)) { pairs[i] = b; pairs[ixj] = a; }
                }
            }
            __syncthreads();
        }
    }

    // softmax over sorted top-1024
    const float vmax = mk2f((uint32_t)(pairs[0] >> 32));
    float myexp[2];
    float psum = 0.f;
#pragma unroll
    for (int r = 0; r < 2; r++) {
        int jj = tid + r * 512;
        float v = mk2f((uint32_t)(pairs[jj] >> 32));
        myexp[r] = expf(v - vmax);
        psum += myexp[r];
    }
    s_red[tid] = psum;
    __syncthreads();
    for (int o = 256; o; o >>= 1) {
        if (tid < o) s_red[tid] += s_red[tid + o];
        __syncthreads();
    }
    const float inv = 1.f / s_red[0];

    const int bud = budget[t];
    const size_t base = (size_t)t * TOPK;
#pragma unroll
    for (int r = 0; r < 2; r++) {
        int jj = tid + r * 512;
        unsigned long long p = pairs[jj];
        uint32_t idx = 0xFFFFFFFFu - (uint32_t)(p & 0xFFFFFFFFull);
        float m = (jj < bud) ? 1.f : 0.f;
        out_idx[base + jj] = (float)idx;
        out_w[base + jj]   = myexp[r] * inv * m;
        out_m[base + jj]   = m;
    }
}

// ---------------- launch -----------------------------------------------------
extern "C" void kernel_launch(void* const* d_in, const int* in_sizes, int n_in,
                              void* d_out, int out_size)
{
    const float* x   = (const float*)d_in[0];
    const float* w1c = (const float*)d_in[1];
    const float* b1c = (const float*)d_in[2];
    const float* w2c = (const float*)d_in[3];
    const float* b2c = (const float*)d_in[4];
    const float* ws1 = (const float*)d_in[5];
    const float* bs1 = (const float*)d_in[6];
    const float* ws2 = (const float*)d_in[7];
    const float* bs2 = (const float*)d_in[8];

    float* out     = (float*)d_out;
    float* out_idx = out;
    float* out_w   = out + (size_t)NTOK * TOPK;
    float* out_m   = out + 2 * (size_t)NTOK * TOPK;
    float* out_c   = out + 3 * (size_t)NTOK * TOPK;

    float *hs_p, *hc_p, *sc_p;
    int   *bud_p;
    cudaGetSymbolAddress((void**)&hs_p,  g_hs);
    cudaGetSymbolAddress((void**)&hc_p,  g_hc);
    cudaGetSymbolAddress((void**)&sc_p,  g_scores);
    cudaGetSymbolAddress((void**)&bud_p, g_budget);

    dim3 blk(256);
    // hs = relu(x @ ws1 + bs1)
    sgemm2_bias<true><<<dim3(HID / 128, NTOK / 128), blk>>>(x, ws1, bs1, hs_p, NTOK, HID, DIM);
    // hc = relu(x @ w1c + b1c)
    sgemm2_bias<true><<<dim3(HIDC / 128, NTOK / 128), blk>>>(x, w1c, b1c, hc_p, NTOK, HIDC, DIM);
    // complexity + budgets
    complexity_kernel<<<NTOK / 8, 256>>>(hc_p, w2c, b2c, out_c, bud_p);
    // scores = hs @ ws2 + bs2
    sgemm2_bias<false><<<dim3(POOL / 128, NTOK / 128), blk>>>(hs_p, ws2, bs2, sc_p, NTOK, POOL, HID);
    // per-token sorted top-k + softmax + mask
    topk_kernel<<<NTOK, 512>>>(sc_p, bud_p, out_idx, out_w, out_m);
}

// round 5
// speedup vs baseline: 1.2409x; 1.2409x over previous
#include <cuda_runtime.h>
#include <cstdint>
#include <math.h>

#define NTOK 8192
#define DIM  1024
#define HID  256
#define HIDC 128
#define POOL 16384
#define TOPK 1024

// ---------------- scratch (device globals: no allocations allowed) ----------
__device__ float g_hs[NTOK * HID];                 // 8 MB
__device__ float g_hc[NTOK * HIDC];                // 4 MB
__device__ float g_scores[(size_t)NTOK * POOL];    // 512 MB
__device__ int   g_budget[NTOK];

// packed fp32x2 FMA (sm_100+): two independent rn-rounded fp32 FMAs per issue.
__device__ __forceinline__ float2 ffma2(float2 a, float2 b, float2 c) {
    unsigned long long A = *(unsigned long long*)&a;
    unsigned long long B = *(unsigned long long*)&b;
    unsigned long long C = *(unsigned long long*)&c;
    unsigned long long D;
    asm("fma.rn.f32x2 %0, %1, %2, %3;" : "=l"(D) : "l"(A), "l"(B), "l"(C));
    return *(float2*)&D;
}

// ---------------- fp32x2 tiled GEMM (R2 version): C = relu?(A@B + bias) -----
// BM=128, BN=128, BK=8, 256 threads, 8x8 outputs/thread. Each output element
// is ONE fp32 FMA chain in increasing k-order (bitwise == reference path).
template<bool RELU>
__global__ void __launch_bounds__(256, 2)
sgemm2_bias(const float* __restrict__ A, const float* __restrict__ B,
            const float* __restrict__ bias, float* __restrict__ C,
            int M, int N, int K)
{
    __shared__ float As[2][8][128];
    __shared__ float Bs[2][8][128];

    const int tid = threadIdx.x;
    const int bm  = blockIdx.y * 128;
    const int bn  = blockIdx.x * 128;
    const int tx  = tid & 15;
    const int ty  = tid >> 4;

    float2 acc[8][4];
#pragma unroll
    for (int i = 0; i < 8; i++)
#pragma unroll
        for (int q = 0; q < 4; q++) acc[i][q] = make_float2(0.f, 0.f);

    const int ar = tid >> 1;
    const int ac = (tid & 1) * 4;
    const int br = tid >> 5;
    const int bc = (tid & 31) * 4;
    const float* Aptr = A + (size_t)(bm + ar) * K + ac;
    const float* Bptr = B + (size_t)br * N + bn + bc;

    const int NT = K >> 3;

    float4 av = *(const float4*)(Aptr);
    float4 bv = *(const float4*)(Bptr);
    As[0][ac + 0][ar] = av.x; As[0][ac + 1][ar] = av.y;
    As[0][ac + 2][ar] = av.z; As[0][ac + 3][ar] = av.w;
    *(float4*)&Bs[0][br][bc] = bv;
    __syncthreads();

    for (int t = 0; t < NT; t++) {
        const int buf = t & 1;
        const bool more = (t + 1) < NT;
        if (more) {
            av = *(const float4*)(Aptr + (t + 1) * 8);
            bv = *(const float4*)(Bptr + (size_t)(t + 1) * 8 * N);
        }

#pragma unroll
        for (int k = 0; k < 8; k++) {
            float4 a0 = *(const float4*)&As[buf][k][ty * 8];
            float4 a1 = *(const float4*)&As[buf][k][ty * 8 + 4];
            float4 b0 = *(const float4*)&Bs[buf][k][tx * 4];
            float4 b1 = *(const float4*)&Bs[buf][k][tx * 4 + 64];
            float2 bp[4];
            bp[0] = make_float2(b0.x, b0.y); bp[1] = make_float2(b0.z, b0.w);
            bp[2] = make_float2(b1.x, b1.y); bp[3] = make_float2(b1.z, b1.w);
            float a[8] = {a0.x, a0.y, a0.z, a0.w, a1.x, a1.y, a1.z, a1.w};
#pragma unroll
            for (int i = 0; i < 8; i++) {
                float2 ad = make_float2(a[i], a[i]);
#pragma unroll
                for (int q = 0; q < 4; q++)
                    acc[i][q] = ffma2(ad, bp[q], acc[i][q]);
            }
        }

        if (more) {
            const int nb = buf ^ 1;
            As[nb][ac + 0][ar] = av.x; As[nb][ac + 1][ar] = av.y;
            As[nb][ac + 2][ar] = av.z; As[nb][ac + 3][ar] = av.w;
            *(float4*)&Bs[nb][br][bc] = bv;
        }
        __syncthreads();
    }

#pragma unroll
    for (int i = 0; i < 8; i++) {
        const int row = bm + ty * 8 + i;
#pragma unroll
        for (int g = 0; g < 2; g++) {
            const int col = bn + tx * 4 + g * 64;
            float4 v;
            v.x = acc[i][g * 2 + 0].x + bias[col + 0];
            v.y = acc[i][g * 2 + 0].y + bias[col + 1];
            v.z = acc[i][g * 2 + 1].x + bias[col + 2];
            v.w = acc[i][g * 2 + 1].y + bias[col + 3];
            if (RELU) {
                v.x = fmaxf(v.x, 0.f); v.y = fmaxf(v.y, 0.f);
                v.z = fmaxf(v.z, 0.f); v.w = fmaxf(v.w, 0.f);
            }
            *(float4*)(C + (size_t)row * N + col) = v;
        }
    }
}

// ---------------- complexity -> sigmoid -> budget ---------------------------
__global__ void complexity_kernel(const float* __restrict__ hc,
                                  const float* __restrict__ w2c,
                                  const float* __restrict__ b2c,
                                  float* __restrict__ out_c,
                                  int* __restrict__ budget)
{
    int warp = (blockIdx.x * blockDim.x + threadIdx.x) >> 5;
    int lane = threadIdx.x & 31;
    if (warp >= NTOK) return;
    const float* h = hc + (size_t)warp * HIDC;
    float s = 0.f;
#pragma unroll
    for (int i = lane; i < HIDC; i += 32) s += h[i] * w2c[i];
#pragma unroll
    for (int o = 16; o; o >>= 1) s += __shfl_xor_sync(0xFFFFFFFFu, s, o);
    if (lane == 0) {
        float z = s + b2c[0];
        float c = 1.f / (1.f + expf(-z));
        out_c[warp] = c;
        float raw = 100.f + 924.f * (c * c);
        raw = fminf(fmaxf(raw, 100.f), 1024.f);
        budget[warp] = (int)rintf(raw);
    }
}

// ---------------- top-k helpers ---------------------------------------------
__device__ __forceinline__ uint32_t f2mk(float f) {
    uint32_t u = __float_as_uint(f);
    return (u & 0x80000000u) ? ~u : (u | 0x80000000u);
}
__device__ __forceinline__ float mk2f(uint32_t mk) {
    uint32_t u = (mk & 0x80000000u) ? (mk ^ 0x80000000u) : ~mk;
    return __uint_as_float(u);
}
__device__ __forceinline__ void cmpsel(unsigned long long& a, unsigned long long b,
                                       bool want_max) {
    bool take = want_max ? (b > a) : (b < a);
    if (take) a = b;
}
// shfl bitonic stage: element stride j = 4*lanexor (cross-thread, same slot)
__device__ __forceinline__ void shfl_stage(unsigned long long v[4], int lanexor,
                                           bool desc, int t) {
    const bool wm = (((t & lanexor) == 0) == desc);
#pragma unroll
    for (int e = 0; e < 4; e++) {
        unsigned long long o = __shfl_xor_sync(0xFFFFFFFFu, v[e], lanexor);
        cmpsel(v[e], o, wm);
    }
}
// intra-thread stage j=2: pairs (0,2),(1,3)
__device__ __forceinline__ void local_j2(unsigned long long v[4], bool desc) {
    unsigned long long a0 = v[0], a2 = v[2];
    cmpsel(v[0], a2, desc);  cmpsel(v[2], a0, !desc);
    unsigned long long a1 = v[1], a3 = v[3];
    cmpsel(v[1], a3, desc);  cmpsel(v[3], a1, !desc);
}
// intra-thread stage j=1: pairs (0,1) dir=d0, (2,3) dir=d1
__device__ __forceinline__ void local_j1(unsigned long long v[4], bool d0, bool d1) {
    unsigned long long a = v[0], b = v[1];
    cmpsel(v[0], b, d0);  cmpsel(v[1], a, !d0);
    unsigned long long c = v[2], d = v[3];
    cmpsel(v[2], d, d1);  cmpsel(v[3], c, !d1);
}
// final 128-merge: j = 64,32,16,8,4 (shfl) then 2,1 (local)
__device__ __forceinline__ void merge128(unsigned long long v[4], bool desc, int t) {
    shfl_stage(v, 16, desc, t);
    shfl_stage(v,  8, desc, t);
    shfl_stage(v,  4, desc, t);
    shfl_stage(v,  2, desc, t);
    shfl_stage(v,  1, desc, t);
    local_j2(v, desc);
    local_j1(v, desc, desc);
}
// cross-warp stage through shared memory (j in {128,256,512,1024})
__device__ __forceinline__ void smem_stage(unsigned long long* sp,
                                           unsigned long long v[4],
                                           int j, bool desc, int t) {
#pragma unroll
    for (int e = 0; e < 4; e++) sp[4 * t + e] = v[e];
    __syncthreads();
    const bool wm = (((t & (j >> 2)) == 0) == desc);
#pragma unroll
    for (int e = 0; e < 4; e++) {
        unsigned long long o = sp[(4 * t + e) ^ j];
        cmpsel(v[e], o, wm);
    }
    __syncthreads();
}

// ---------------- per-token top-1024 (sorted) + softmax + mask --------------
__global__ void __launch_bounds__(512)
topk_kernel(const float* __restrict__ scores, const int* __restrict__ budget,
            float* __restrict__ out_idx, float* __restrict__ out_w,
            float* __restrict__ out_m)
{
    __shared__ uint32_t hist[4096];
    __shared__ unsigned long long pairs[2048];
    __shared__ uint32_t chunksum[256];
    __shared__ uint32_t s_bstar, s_cnt;
    __shared__ float    s_red[512];

    const int t   = blockIdx.x;
    const int tid = threadIdx.x;
    const float4* row4 = (const float4*)(scores + (size_t)t * POOL);

    uint32_t cnt = 0;
    bool     use_sample = true;
    uint32_t target = 192;                 // expected survivors ~= 8*192 = 1536

    for (int attempt = 0; attempt < 2; attempt++) {
        for (int i = tid; i < 4096; i += 512) hist[i] = 0;
        if (tid == 0) s_cnt = 0;
        __syncthreads();

        // histogram over sample (1/8 stride) or full data
        if (use_sample) {
            float4 v = row4[tid * 8];
            atomicAdd(&hist[f2mk(v.x) >> 20], 1u);
            atomicAdd(&hist[f2mk(v.y) >> 20], 1u);
            atomicAdd(&hist[f2mk(v.z) >> 20], 1u);
            atomicAdd(&hist[f2mk(v.w) >> 20], 1u);
        } else {
#pragma unroll
            for (int s = 0; s < 8; s++) {
                float4 v = row4[tid + s * 512];
                atomicAdd(&hist[f2mk(v.x) >> 20], 1u);
                atomicAdd(&hist[f2mk(v.y) >> 20], 1u);
                atomicAdd(&hist[f2mk(v.z) >> 20], 1u);
                atomicAdd(&hist[f2mk(v.w) >> 20], 1u);
            }
        }
        __syncthreads();

        // chunk sums + suffix scan (chunksum[c] = sum of bins >= 16c)
        if (tid < 256) {
            uint32_t cs = 0;
#pragma unroll
            for (int b = tid * 16; b < tid * 16 + 16; b++) cs += hist[b];
            chunksum[tid] = cs;
        }
        __syncthreads();
        for (int off = 1; off < 256; off <<= 1) {
            uint32_t add = 0;
            if (tid < 256 && tid + off < 256) add = chunksum[tid + off];
            __syncthreads();
            if (tid < 256) chunksum[tid] += add;
            __syncthreads();
        }
        // unique crossing chunk: S(c) >= target > S(c+1); refine within chunk
        if (tid < 256) {
            uint32_t Sc = chunksum[tid];
            uint32_t Sn = (tid < 255) ? chunksum[tid + 1] : 0;
            if (Sc >= target && Sn < target) {
                uint32_t cum = Sn;
                int b;
                for (b = tid * 16 + 15; b > tid * 16; b--) {
                    cum += hist[b];
                    if (cum >= target) break;
                }
                s_bstar = (uint32_t)b;
            }
        }
        __syncthreads();
        const uint32_t bstar = s_bstar;

        // compact survivors (full data); key: desc value, asc index
#pragma unroll
        for (int s = 0; s < 8; s++) {
            int i4 = tid + s * 512;
            float4 v = row4[i4];
            float vals[4] = {v.x, v.y, v.z, v.w};
#pragma unroll
            for (int e = 0; e < 4; e++) {
                uint32_t mk = f2mk(vals[e]);
                if ((mk >> 20) >= bstar) {
                    uint32_t pos = atomicAdd(&s_cnt, 1u);
                    if (pos < 2048) {
                        uint32_t idx = (uint32_t)(i4 * 4 + e);
                        pairs[pos] = ((unsigned long long)mk << 32) |
                                     (unsigned long long)(0xFFFFFFFFu - idx);
                    }
                }
            }
        }
        __syncthreads();
        cnt = s_cnt;
        if (cnt >= (uint32_t)TOPK && cnt <= 2048u) break;
        // fallback: exact histogram, minimal threshold covering TOPK
        use_sample = false;
        target = TOPK;
        __syncthreads();
    }
    if (cnt > 2048u) cnt = 2048u;

    // pad
    for (int i = tid; i < 2048; i += 512)
        if ((uint32_t)i >= cnt) pairs[i] = 0ull;
    __syncthreads();

    // ---- hybrid bitonic sort, 2048 u64 descending; 4 elems/thread ----------
    unsigned long long v[4];
#pragma unroll
    for (int e = 0; e < 4; e++) v[e] = pairs[4 * tid + e];

    // phase 1: k = 2 .. 128 (register/shfl only)
    local_j1(v, true, false);                                  // k=2
    { bool d = ((tid & 1) == 0);                               // k=4
      local_j2(v, d); local_j1(v, d, d); }
    { bool d = ((tid & 2) == 0);                               // k=8
      shfl_stage(v, 1, d, tid);
      local_j2(v, d); local_j1(v, d, d); }
    { bool d = ((tid & 4) == 0);                               // k=16
      shfl_stage(v, 2, d, tid); shfl_stage(v, 1, d, tid);
      local_j2(v, d); local_j1(v, d, d); }
    { bool d = ((tid & 8) == 0);                               // k=32
      shfl_stage(v, 4, d, tid); shfl_stage(v, 2, d, tid); shfl_stage(v, 1, d, tid);
      local_j2(v, d); local_j1(v, d, d); }
    { bool d = ((tid & 16) == 0);                              // k=64
      shfl_stage(v, 8, d, tid); shfl_stage(v, 4, d, tid);
      shfl_stage(v, 2, d, tid); shfl_stage(v, 1, d, tid);
      local_j2(v, d); local_j1(v, d, d); }
    { bool d = ((tid & 32) == 0);                              // k=128
      merge128(v, d, tid); }

    // phase 2: k = 256 .. 2048 (smem for j >= 128, then local merge)
    { bool d = ((tid & 64) == 0);                              // k=256
      smem_stage(pairs, v, 128, d, tid);
      merge128(v, d, tid); }
    { bool d = ((tid & 128) == 0);                             // k=512
      smem_stage(pairs, v, 256, d, tid);
      smem_stage(pairs, v, 128, d, tid);
      merge128(v, d, tid); }
    { bool d = ((tid & 256) == 0);                             // k=1024
      smem_stage(pairs, v, 512, d, tid);
      smem_stage(pairs, v, 256, d, tid);
      smem_stage(pairs, v, 128, d, tid);
      merge128(v, d, tid); }
    {                                                          // k=2048 (desc)
      smem_stage(pairs, v, 1024, true, tid);
      smem_stage(pairs, v,  512, true, tid);
      smem_stage(pairs, v,  256, true, tid);
      smem_stage(pairs, v,  128, true, tid);
      merge128(v, true, tid); }

#pragma unroll
    for (int e = 0; e < 4; e++) pairs[4 * tid + e] = v[e];
    __syncthreads();

    // ---- softmax over sorted top-1024 + budget mask -------------------------
    const float vmax = mk2f((uint32_t)(pairs[0] >> 32));
    float myexp[2];
    float psum = 0.f;
#pragma unroll
    for (int r = 0; r < 2; r++) {
        int jj = tid + r * 512;
        float vv = mk2f((uint32_t)(pairs[jj] >> 32));
        myexp[r] = expf(vv - vmax);
        psum += myexp[r];
    }
    s_red[tid] = psum;
    __syncthreads();
    for (int o = 256; o; o >>= 1) {
        if (tid < o) s_red[tid] += s_red[tid + o];
        __syncthreads();
    }
    const float inv = 1.f / s_red[0];

    const int bud = budget[t];
    const size_t base = (size_t)t * TOPK;
#pragma unroll
    for (int r = 0; r < 2; r++) {
        int jj = tid + r * 512;
        unsigned long long p = pairs[jj];
        uint32_t idx = 0xFFFFFFFFu - (uint32_t)(p & 0xFFFFFFFFull);
        float m = (jj < bud) ? 1.f : 0.f;
        out_idx[base + jj] = (float)idx;
        out_w[base + jj]   = myexp[r] * inv * m;
        out_m[base + jj]   = m;
    }
}

// ---------------- launch -----------------------------------------------------
extern "C" void kernel_launch(void* const* d_in, const int* in_sizes, int n_in,
                              void* d_out, int out_size)
{
    const float* x   = (const float*)d_in[0];
    const float* w1c = (const float*)d_in[1];
    const float* b1c = (const float*)d_in[2];
    const float* w2c = (const float*)d_in[3];
    const float* b2c = (const float*)d_in[4];
    const float* ws1 = (const float*)d_in[5];
    const float* bs1 = (const float*)d_in[6];
    const float* ws2 = (const float*)d_in[7];
    const float* bs2 = (const float*)d_in[8];

    float* out     = (float*)d_out;
    float* out_idx = out;
    float* out_w   = out + (size_t)NTOK * TOPK;
    float* out_m   = out + 2 * (size_t)NTOK * TOPK;
    float* out_c   = out + 3 * (size_t)NTOK * TOPK;

    float *hs_p, *hc_p, *sc_p;
    int   *bud_p;
    cudaGetSymbolAddress((void**)&hs_p,  g_hs);
    cudaGetSymbolAddress((void**)&hc_p,  g_hc);
    cudaGetSymbolAddress((void**)&sc_p,  g_scores);
    cudaGetSymbolAddress((void**)&bud_p, g_budget);

    dim3 blk(256);
    // hs = relu(x @ ws1 + bs1)
    sgemm2_bias<true><<<dim3(HID / 128, NTOK / 128), blk>>>(x, ws1, bs1, hs_p, NTOK, HID, DIM);
    // hc = relu(x @ w1c + b1c)
    sgemm2_bias<true><<<dim3(HIDC / 128, NTOK / 128), blk>>>(x, w1c, b1c, hc_p, NTOK, HIDC, DIM);
    // complexity + budgets
    complexity_kernel<<<NTOK / 8, 256>>>(hc_p, w2c, b2c, out_c, bud_p);
    // scores = hs @ ws2 + bs2
    sgemm2_bias<false><<<dim3(POOL / 128, NTOK / 128), blk>>>(hs_p, ws2, bs2, sc_p, NTOK, POOL, HID);
    // per-token sorted top-k + softmax + mask
    topk_kernel<<<NTOK, 512>>>(sc_p, bud_p, out_idx, out_w, out_m);
}

// round 6
// speedup vs baseline: 1.2571x; 1.0131x over previous
#include <cuda_runtime.h>
#include <cstdint>
#include <math.h>

#define NTOK 8192
#define DIM  1024
#define HID  256
#define HIDC 128
#define POOL 16384
#define TOPK 1024

// ---------------- scratch (device globals: no allocations allowed) ----------
__device__ float g_hs[NTOK * HID];                 // 8 MB
__device__ float g_hc[NTOK * HIDC];                // 4 MB
__device__ float g_scores[(size_t)NTOK * POOL];    // 512 MB
__device__ int   g_budget[NTOK];

// packed fp32x2 FMA (sm_100+): two independent rn-rounded fp32 FMAs per issue.
__device__ __forceinline__ float2 ffma2(float2 a, float2 b, float2 c) {
    unsigned long long A = *(unsigned long long*)&a;
    unsigned long long B = *(unsigned long long*)&b;
    unsigned long long C = *(unsigned long long*)&c;
    unsigned long long D;
    asm("fma.rn.f32x2 %0, %1, %2, %3;" : "=l"(D) : "l"(A), "l"(B), "l"(C));
    return *(float2*)&D;
}

// ---------------- fp32x2 tiled GEMM (proven R2 version) ---------------------
template<bool RELU>
__global__ void __launch_bounds__(256, 2)
sgemm2_bias(const float* __restrict__ A, const float* __restrict__ B,
            const float* __restrict__ bias, float* __restrict__ C,
            int M, int N, int K)
{
    __shared__ float As[2][8][128];
    __shared__ float Bs[2][8][128];

    const int tid = threadIdx.x;
    const int bm  = blockIdx.y * 128;
    const int bn  = blockIdx.x * 128;
    const int tx  = tid & 15;
    const int ty  = tid >> 4;

    float2 acc[8][4];
#pragma unroll
    for (int i = 0; i < 8; i++)
#pragma unroll
        for (int q = 0; q < 4; q++) acc[i][q] = make_float2(0.f, 0.f);

    const int ar = tid >> 1;
    const int ac = (tid & 1) * 4;
    const int br = tid >> 5;
    const int bc = (tid & 31) * 4;
    const float* Aptr = A + (size_t)(bm + ar) * K + ac;
    const float* Bptr = B + (size_t)br * N + bn + bc;

    const int NT = K >> 3;

    float4 av = *(const float4*)(Aptr);
    float4 bv = *(const float4*)(Bptr);
    As[0][ac + 0][ar] = av.x; As[0][ac + 1][ar] = av.y;
    As[0][ac + 2][ar] = av.z; As[0][ac + 3][ar] = av.w;
    *(float4*)&Bs[0][br][bc] = bv;
    __syncthreads();

    for (int t = 0; t < NT; t++) {
        const int buf = t & 1;
        const bool more = (t + 1) < NT;
        if (more) {
            av = *(const float4*)(Aptr + (t + 1) * 8);
            bv = *(const float4*)(Bptr + (size_t)(t + 1) * 8 * N);
        }

#pragma unroll
        for (int k = 0; k < 8; k++) {
            float4 a0 = *(const float4*)&As[buf][k][ty * 8];
            float4 a1 = *(const float4*)&As[buf][k][ty * 8 + 4];
            float4 b0 = *(const float4*)&Bs[buf][k][tx * 4];
            float4 b1 = *(const float4*)&Bs[buf][k][tx * 4 + 64];
            float2 bp[4];
            bp[0] = make_float2(b0.x, b0.y); bp[1] = make_float2(b0.z, b0.w);
            bp[2] = make_float2(b1.x, b1.y); bp[3] = make_float2(b1.z, b1.w);
            float a[8] = {a0.x, a0.y, a0.z, a0.w, a1.x, a1.y, a1.z, a1.w};
#pragma unroll
            for (int i = 0; i < 8; i++) {
                float2 ad = make_float2(a[i], a[i]);
#pragma unroll
                for (int q = 0; q < 4; q++)
                    acc[i][q] = ffma2(ad, bp[q], acc[i][q]);
            }
        }

        if (more) {
            const int nb = buf ^ 1;
            As[nb][ac + 0][ar] = av.x; As[nb][ac + 1][ar] = av.y;
            As[nb][ac + 2][ar] = av.z; As[nb][ac + 3][ar] = av.w;
            *(float4*)&Bs[nb][br][bc] = bv;
        }
        __syncthreads();
    }

#pragma unroll
    for (int i = 0; i < 8; i++) {
        const int row = bm + ty * 8 + i;
#pragma unroll
        for (int g = 0; g < 2; g++) {
            const int col = bn + tx * 4 + g * 64;
            float4 v;
            v.x = acc[i][g * 2 + 0].x + bias[col + 0];
            v.y = acc[i][g * 2 + 0].y + bias[col + 1];
            v.z = acc[i][g * 2 + 1].x + bias[col + 2];
            v.w = acc[i][g * 2 + 1].y + bias[col + 3];
            if (RELU) {
                v.x = fmaxf(v.x, 0.f); v.y = fmaxf(v.y, 0.f);
                v.z = fmaxf(v.z, 0.f); v.w = fmaxf(v.w, 0.f);
            }
            *(float4*)(C + (size_t)row * N + col) = v;
        }
    }
}

// ---------------- complexity -> sigmoid -> budget ---------------------------
__global__ void complexity_kernel(const float* __restrict__ hc,
                                  const float* __restrict__ w2c,
                                  const float* __restrict__ b2c,
                                  float* __restrict__ out_c,
                                  int* __restrict__ budget)
{
    int warp = (blockIdx.x * blockDim.x + threadIdx.x) >> 5;
    int lane = threadIdx.x & 31;
    if (warp >= NTOK) return;
    const float* h = hc + (size_t)warp * HIDC;
    float s = 0.f;
#pragma unroll
    for (int i = lane; i < HIDC; i += 32) s += h[i] * w2c[i];
#pragma unroll
    for (int o = 16; o; o >>= 1) s += __shfl_xor_sync(0xFFFFFFFFu, s, o);
    if (lane == 0) {
        float z = s + b2c[0];
        float c = 1.f / (1.f + expf(-z));
        out_c[warp] = c;
        float raw = 100.f + 924.f * (c * c);
        raw = fminf(fmaxf(raw, 100.f), 1024.f);
        budget[warp] = (int)rintf(raw);
    }
}

// ---------------- top-k helpers ---------------------------------------------
__device__ __forceinline__ uint32_t f2mk(float f) {
    uint32_t u = __float_as_uint(f);
    return (u & 0x80000000u) ? ~u : (u | 0x80000000u);
}
__device__ __forceinline__ float mk2f(uint32_t mk) {
    uint32_t u = (mk & 0x80000000u) ? (mk ^ 0x80000000u) : ~mk;
    return __uint_as_float(u);
}
// bank-spread swizzle for the u64 pairs array (involution, bijection on [0,2048))
__device__ __forceinline__ int swz(int i) { return i ^ ((i >> 4) & 15); }

__device__ __forceinline__ void cmpsel(unsigned long long& a, unsigned long long b,
                                       bool want_max) {
    bool take = want_max ? (b > a) : (b < a);
    if (take) a = b;
}
__device__ __forceinline__ void shfl_stage(unsigned long long v[4], int lanexor,
                                           bool desc, int t) {
    const bool wm = (((t & lanexor) == 0) == desc);
#pragma unroll
    for (int e = 0; e < 4; e++) {
        unsigned long long o = __shfl_xor_sync(0xFFFFFFFFu, v[e], lanexor);
        cmpsel(v[e], o, wm);
    }
}
__device__ __forceinline__ void local_j2(unsigned long long v[4], bool desc) {
    unsigned long long a0 = v[0], a2 = v[2];
    cmpsel(v[0], a2, desc);  cmpsel(v[2], a0, !desc);
    unsigned long long a1 = v[1], a3 = v[3];
    cmpsel(v[1], a3, desc);  cmpsel(v[3], a1, !desc);
}
__device__ __forceinline__ void local_j1(unsigned long long v[4], bool d0, bool d1) {
    unsigned long long a = v[0], b = v[1];
    cmpsel(v[0], b, d0);  cmpsel(v[1], a, !d0);
    unsigned long long c = v[2], d = v[3];
    cmpsel(v[2], d, d1);  cmpsel(v[3], c, !d1);
}
__device__ __forceinline__ void merge128(unsigned long long v[4], bool desc, int t) {
    shfl_stage(v, 16, desc, t);
    shfl_stage(v,  8, desc, t);
    shfl_stage(v,  4, desc, t);
    shfl_stage(v,  2, desc, t);
    shfl_stage(v,  1, desc, t);
    local_j2(v, desc);
    local_j1(v, desc, desc);
}
__device__ __forceinline__ void smem_stage(unsigned long long* sp,
                                           unsigned long long v[4],
                                           int j, bool desc, int t) {
#pragma unroll
    for (int e = 0; e < 4; e++) sp[swz(4 * t + e)] = v[e];
    __syncthreads();
    const bool wm = (((t & (j >> 2)) == 0) == desc);
#pragma unroll
    for (int e = 0; e < 4; e++) {
        unsigned long long o = sp[swz((4 * t + e) ^ j)];
        cmpsel(v[e], o, wm);
    }
    __syncthreads();
}

// ---------------- per-token top-1024 (sorted) + softmax + mask --------------
__global__ void __launch_bounds__(512, 2)
topk_kernel(const float* __restrict__ scores, const int* __restrict__ budget,
            float* __restrict__ out_idx, float* __restrict__ out_w,
            float* __restrict__ out_m)
{
    __shared__ uint32_t hist[4096];
    __shared__ unsigned long long pairs[2048];
    __shared__ uint32_t chunksum[256];
    __shared__ uint32_t s_bstar, s_cnt;
    __shared__ float    s_red[512];

    const int t    = blockIdx.x;
    const int tid  = threadIdx.x;
    const int lane = tid & 31;
    const uint32_t lt_mask = (1u << lane) - 1u;
    const float4* row4 = (const float4*)(scores + (size_t)t * POOL);

    uint32_t cnt = 0;
    bool     use_sample = true;
    uint32_t target = 192;                 // expected survivors ~= 8*192 = 1536

    for (int attempt = 0; attempt < 2; attempt++) {
        for (int i = tid; i < 4096; i += 512) hist[i] = 0;
        if (tid == 0) s_cnt = 0;
        __syncthreads();

        if (use_sample) {
            float4 v = row4[tid * 8];
            atomicAdd(&hist[f2mk(v.x) >> 20], 1u);
            atomicAdd(&hist[f2mk(v.y) >> 20], 1u);
            atomicAdd(&hist[f2mk(v.z) >> 20], 1u);
            atomicAdd(&hist[f2mk(v.w) >> 20], 1u);
        } else {
#pragma unroll
            for (int s = 0; s < 8; s++) {
                float4 v = row4[tid + s * 512];
                atomicAdd(&hist[f2mk(v.x) >> 20], 1u);
                atomicAdd(&hist[f2mk(v.y) >> 20], 1u);
                atomicAdd(&hist[f2mk(v.z) >> 20], 1u);
                atomicAdd(&hist[f2mk(v.w) >> 20], 1u);
            }
        }
        __syncthreads();

        if (tid < 256) {
            uint32_t cs = 0;
#pragma unroll
            for (int b = tid * 16; b < tid * 16 + 16; b++) cs += hist[b];
            chunksum[tid] = cs;
        }
        __syncthreads();
        for (int off = 1; off < 256; off <<= 1) {
            uint32_t add = 0;
            if (tid < 256 && tid + off < 256) add = chunksum[tid + off];
            __syncthreads();
            if (tid < 256) chunksum[tid] += add;
            __syncthreads();
        }
        if (tid < 256) {
            uint32_t Sc = chunksum[tid];
            uint32_t Sn = (tid < 255) ? chunksum[tid + 1] : 0;
            if (Sc >= target && Sn < target) {
                uint32_t cum = Sn;
                int b;
                for (b = tid * 16 + 15; b > tid * 16; b--) {
                    cum += hist[b];
                    if (cum >= target) break;
                }
                s_bstar = (uint32_t)b;
            }
        }
        __syncthreads();
        const uint32_t bstar = s_bstar;

        // compact survivors; warp-aggregated atomics; batched loads (MLP=4)
#pragma unroll
        for (int half = 0; half < 2; half++) {
            float4 vv[4];
#pragma unroll
            for (int s = 0; s < 4; s++)
                vv[s] = row4[tid + (half * 4 + s) * 512];
#pragma unroll
            for (int s = 0; s < 4; s++) {
                const int i4 = tid + (half * 4 + s) * 512;
                float vals[4] = {vv[s].x, vv[s].y, vv[s].z, vv[s].w};
#pragma unroll
                for (int e = 0; e < 4; e++) {
                    uint32_t mk = f2mk(vals[e]);
                    bool pred = (mk >> 20) >= bstar;
                    uint32_t bal = __ballot_sync(0xFFFFFFFFu, pred);
                    uint32_t base = 0;
                    if (lane == 0 && bal)
                        base = atomicAdd(&s_cnt, (uint32_t)__popc(bal));
                    base = __shfl_sync(0xFFFFFFFFu, base, 0);
                    if (pred) {
                        uint32_t pos = base + (uint32_t)__popc(bal & lt_mask);
                        if (pos < 2048) {
                            uint32_t idx = (uint32_t)(i4 * 4 + e);
                            pairs[swz((int)pos)] =
                                ((unsigned long long)mk << 32) |
                                (unsigned long long)(0xFFFFFFFFu - idx);
                        }
                    }
                }
            }
        }
        __syncthreads();
        cnt = s_cnt;
        if (cnt >= (uint32_t)TOPK && cnt <= 2048u) break;
        use_sample = false;
        target = TOPK;
        __syncthreads();
    }
    if (cnt > 2048u) cnt = 2048u;

    for (int i = tid; i < 2048; i += 512)
        if ((uint32_t)i >= cnt) pairs[swz(i)] = 0ull;
    __syncthreads();

    // ---- hybrid bitonic sort, 2048 u64 descending; 4 elems/thread ----------
    unsigned long long v[4];
#pragma unroll
    for (int e = 0; e < 4; e++) v[e] = pairs[swz(4 * tid + e)];

    local_j1(v, true, false);                                  // k=2
    { bool d = ((tid & 1) == 0);                               // k=4
      local_j2(v, d); local_j1(v, d, d); }
    { bool d = ((tid & 2) == 0);                               // k=8
      shfl_stage(v, 1, d, tid);
      local_j2(v, d); local_j1(v, d, d); }
    { bool d = ((tid & 4) == 0);                               // k=16
      shfl_stage(v, 2, d, tid); shfl_stage(v, 1, d, tid);
      local_j2(v, d); local_j1(v, d, d); }
    { bool d = ((tid & 8) == 0);                               // k=32
      shfl_stage(v, 4, d, tid); shfl_stage(v, 2, d, tid); shfl_stage(v, 1, d, tid);
      local_j2(v, d); local_j1(v, d, d); }
    { bool d = ((tid & 16) == 0);                              // k=64
      shfl_stage(v, 8, d, tid); shfl_stage(v, 4, d, tid);
      shfl_stage(v, 2, d, tid); shfl_stage(v, 1, d, tid);
      local_j2(v, d); local_j1(v, d, d); }
    { bool d = ((tid & 32) == 0);                              // k=128
      merge128(v, d, tid); }

    { bool d = ((tid & 64) == 0);                              // k=256
      smem_stage(pairs, v, 128, d, tid);
      merge128(v, d, tid); }
    { bool d = ((tid & 128) == 0);                             // k=512
      smem_stage(pairs, v, 256, d, tid);
      smem_stage(pairs, v, 128, d, tid);
      merge128(v, d, tid); }
    { bool d = ((tid & 256) == 0);                             // k=1024
      smem_stage(pairs, v, 512, d, tid);
      smem_stage(pairs, v, 256, d, tid);
      smem_stage(pairs, v, 128, d, tid);
      merge128(v, d, tid); }
    {                                                          // k=2048 (desc)
      smem_stage(pairs, v, 1024, true, tid);
      smem_stage(pairs, v,  512, true, tid);
      smem_stage(pairs, v,  256, true, tid);
      smem_stage(pairs, v,  128, true, tid);
      merge128(v, true, tid); }

#pragma unroll
    for (int e = 0; e < 4; e++) pairs[swz(4 * tid + e)] = v[e];
    __syncthreads();

    // ---- softmax over sorted top-1024 + budget mask -------------------------
    const float vmax = mk2f((uint32_t)(pairs[swz(0)] >> 32));
    float myexp[2];
    float psum = 0.f;
    unsigned long long p0 = pairs[swz(tid)];
    unsigned long long p1 = pairs[swz(tid + 512)];
    myexp[0] = expf(mk2f((uint32_t)(p0 >> 32)) - vmax);
    myexp[1] = expf(mk2f((uint32_t)(p1 >> 32)) - vmax);
    psum = myexp[0] + myexp[1];
    s_red[tid] = psum;
    __syncthreads();
    for (int o = 256; o; o >>= 1) {
        if (tid < o) s_red[tid] += s_red[tid + o];
        __syncthreads();
    }
    const float inv = 1.f / s_red[0];

    const int bud = budget[t];
    const size_t base = (size_t)t * TOPK;
    {
        uint32_t idx0 = 0xFFFFFFFFu - (uint32_t)(p0 & 0xFFFFFFFFull);
        float m0 = (tid < bud) ? 1.f : 0.f;
        out_idx[base + tid] = (float)idx0;
        out_w[base + tid]   = myexp[0] * inv * m0;
        out_m[base + tid]   = m0;
        uint32_t idx1 = 0xFFFFFFFFu - (uint32_t)(p1 & 0xFFFFFFFFull);
        int jj = tid + 512;
        float m1 = (jj < bud) ? 1.f : 0.f;
        out_idx[base + jj] = (float)idx1;
        out_w[base + jj]   = myexp[1] * inv * m1;
        out_m[base + jj]   = m1;
    }
}

// ---------------- launch -----------------------------------------------------
extern "C" void kernel_launch(void* const* d_in, const int* in_sizes, int n_in,
                              void* d_out, int out_size)
{
    const float* x   = (const float*)d_in[0];
    const float* w1c = (const float*)d_in[1];
    const float* b1c = (const float*)d_in[2];
    const float* w2c = (const float*)d_in[3];
    const float* b2c = (const float*)d_in[4];
    const float* ws1 = (const float*)d_in[5];
    const float* bs1 = (const float*)d_in[6];
    const float* ws2 = (const float*)d_in[7];
    const float* bs2 = (const float*)d_in[8];

    float* out     = (float*)d_out;
    float* out_idx = out;
    float* out_w   = out + (size_t)NTOK * TOPK;
    float* out_m   = out + 2 * (size_t)NTOK * TOPK;
    float* out_c   = out + 3 * (size_t)NTOK * TOPK;

    float *hs_p, *hc_p, *sc_p;
    int   *bud_p;
    cudaGetSymbolAddress((void**)&hs_p,  g_hs);
    cudaGetSymbolAddress((void**)&hc_p,  g_hc);
    cudaGetSymbolAddress((void**)&sc_p,  g_scores);
    cudaGetSymbolAddress((void**)&bud_p, g_budget);

    dim3 blk(256);
    sgemm2_bias<true><<<dim3(HID / 128, NTOK / 128), blk>>>(x, ws1, bs1, hs_p, NTOK, HID, DIM);
    sgemm2_bias<true><<<dim3(HIDC / 128, NTOK / 128), blk>>>(x, w1c, b1c, hc_p, NTOK, HIDC, DIM);
    complexity_kernel<<<NTOK / 8, 256>>>(hc_p, w2c, b2c, out_c, bud_p);
    sgemm2_bias<false><<<dim3(POOL / 128, NTOK / 128), blk>>>(hs_p, ws2, bs2, sc_p, NTOK, POOL, HID);
    topk_kernel<<<NTOK, 512>>>(sc_p, bud_p, out_idx, out_w, out_m);
}